// round 1
// baseline (speedup 1.0000x reference)
#include <cuda_runtime.h>
#include <math.h>

// Problem constants: B=4, K=64, L=128, D=768
#define NBK   256      // B*K
#define LL    128
#define DD    768
#define NROWS 65536    // NBK * 2 * LL  (all ctx rows + all ent rows)
#define NOUT  32768    // NBK * LL
#define TP    132      // padded smem stride (16B-aligned rows, reduced conflicts)
#define EPSV  1e-8f

// Scratch (device globals; no allocation allowed)
__device__ float g_norm[NROWS];
__device__ int   g_arg[NOUT];
__device__ float g_y[NROWS];

// ---------------------------------------------------------------------------
// Kernel 1: L2 norm of every 768-float row (ctx and ent interleaved per bk)
// one warp per row
// ---------------------------------------------------------------------------
__global__ void norms_kernel(const float* __restrict__ x) {
    int row  = blockIdx.x * 8 + (threadIdx.x >> 5);
    int lane = threadIdx.x & 31;
    const float4* p = reinterpret_cast<const float4*>(x) + (size_t)row * (DD / 4);
    float s = 0.f;
    #pragma unroll
    for (int i = 0; i < 6; i++) {
        float4 v = p[lane + i * 32];
        s += v.x * v.x + v.y * v.y + v.z * v.z + v.w * v.w;
    }
    #pragma unroll
    for (int o = 16; o; o >>= 1) s += __shfl_xor_sync(0xffffffffu, s, o);
    if (lane == 0) g_norm[row] = sqrtf(s);
}

// ---------------------------------------------------------------------------
// Kernel 2: per (b,k): scores[l][m] = <ctx_l, ent_m> / (n_l*n_m + eps),
// argmax over m with first-index tie-break. 128x128x768 GEMM per block.
// ---------------------------------------------------------------------------
__global__ __launch_bounds__(256) void scores_argmax_kernel(const float* __restrict__ x) {
    __shared__ float sm[2 * 32 * TP];
    float* As = sm;             // [32][TP]  ctx^T chunk
    float* Bs = sm + 32 * TP;   // [32][TP]  ent^T chunk

    int bk = blockIdx.x;
    const float* ctx = x + (size_t)(bk * 2) * LL * DD;
    const float* ent = ctx + (size_t)LL * DD;

    int t  = threadIdx.x;
    int tx = t & 15;
    int ty = t >> 4;

    float C[8][8];
    #pragma unroll
    for (int a = 0; a < 8; a++)
        #pragma unroll
        for (int b = 0; b < 8; b++) C[a][b] = 0.f;

    for (int d0 = 0; d0 < DD; d0 += 32) {
        // transpose-load ctx chunk -> As[k][l], ent chunk -> Bs[k][m]
        #pragma unroll
        for (int it = 0; it < 4; it++) {
            int idx = t + it * 256;
            int i  = idx >> 3;      // row 0..127
            int k4 = idx & 7;       // float4 index within 32-d chunk
            float4 v = *reinterpret_cast<const float4*>(ctx + (size_t)i * DD + d0 + k4 * 4);
            As[(k4 * 4 + 0) * TP + i] = v.x;
            As[(k4 * 4 + 1) * TP + i] = v.y;
            As[(k4 * 4 + 2) * TP + i] = v.z;
            As[(k4 * 4 + 3) * TP + i] = v.w;
            float4 w = *reinterpret_cast<const float4*>(ent + (size_t)i * DD + d0 + k4 * 4);
            Bs[(k4 * 4 + 0) * TP + i] = w.x;
            Bs[(k4 * 4 + 1) * TP + i] = w.y;
            Bs[(k4 * 4 + 2) * TP + i] = w.z;
            Bs[(k4 * 4 + 3) * TP + i] = w.w;
        }
        __syncthreads();
        #pragma unroll 8
        for (int kk = 0; kk < 32; kk++) {
            float a[8], b[8];
            #pragma unroll
            for (int i = 0; i < 8; i++) a[i] = As[kk * TP + ty * 8 + i];
            #pragma unroll
            for (int j = 0; j < 8; j++) b[j] = Bs[kk * TP + tx * 8 + j];
            #pragma unroll
            for (int i = 0; i < 8; i++)
                #pragma unroll
                for (int j = 0; j < 8; j++) C[i][j] += a[i] * b[j];
        }
        __syncthreads();
    }

    // epilogue: scale by denom, local argmax per row (m ascending => first max)
    float nl[8], nm[8];
    #pragma unroll
    for (int a = 0; a < 8; a++) nl[a] = g_norm[(bk * 2) * LL + ty * 8 + a];
    #pragma unroll
    for (int b = 0; b < 8; b++) nm[b] = g_norm[(bk * 2 + 1) * LL + tx * 8 + b];

    float bestv[8];
    int   besti[8];
    #pragma unroll
    for (int a = 0; a < 8; a++) { bestv[a] = -3.4e38f; besti[a] = 0; }
    #pragma unroll
    for (int b = 0; b < 8; b++) {
        #pragma unroll
        for (int a = 0; a < 8; a++) {
            float s = C[a][b] / (nl[a] * nm[b] + EPSV);
            if (s > bestv[a]) { bestv[a] = s; besti[a] = tx * 8 + b; }
        }
    }

    // cross-tx reduction (tx ascending preserves first-index tie-break)
    float* rv = sm;                                // 128*16 floats
    int*   ri = reinterpret_cast<int*>(sm + 128 * 16);
    #pragma unroll
    for (int a = 0; a < 8; a++) {
        rv[(ty * 8 + a) * 16 + tx] = bestv[a];
        ri[(ty * 8 + a) * 16 + tx] = besti[a];
    }
    __syncthreads();
    if (t < 128) {
        float bv = -3.4e38f; int bi = 0;
        #pragma unroll
        for (int j = 0; j < 16; j++) {
            float v = rv[t * 16 + j];
            if (v > bv) { bv = v; bi = ri[t * 16 + j]; }
        }
        g_arg[bk * LL + t] = bi;
    }
}

// ---------------------------------------------------------------------------
// Kernel 3: fused MLP scalar per normalized row:
//   y[r] = relu( (x_r / ||x_r||) @ W1 + b1 ) @ w2 + b2
// Block handles 128 rows; loops over 6 e-chunks of 128, GEMM over D=768.
// ---------------------------------------------------------------------------
__global__ __launch_bounds__(256) void mlp_kernel(const float* __restrict__ x,
                                                  const float* __restrict__ w1,
                                                  const float* __restrict__ b1,
                                                  const float* __restrict__ w2,
                                                  const float* __restrict__ b2) {
    __shared__ float sm[2 * 32 * TP];
    __shared__ float sinv[128];
    float* As = sm;
    float* Bs = sm + 32 * TP;

    int rt = blockIdx.x;  // row tile of 128
    const float* X = x + (size_t)rt * LL * DD;

    int t  = threadIdx.x;
    int tx = t & 15;
    int ty = t >> 4;

    if (t < 128) sinv[t] = 1.0f / g_norm[rt * LL + t];
    __syncthreads();

    float yacc[8];
    #pragma unroll
    for (int a = 0; a < 8; a++) yacc[a] = 0.f;

    for (int ec = 0; ec < 6; ec++) {
        float C[8][8];
        #pragma unroll
        for (int a = 0; a < 8; a++)
            #pragma unroll
            for (int b = 0; b < 8; b++) C[a][b] = 0.f;

        for (int d0 = 0; d0 < DD; d0 += 32) {
            // transpose-load X chunk (scaled by 1/norm) -> As[k][row]
            #pragma unroll
            for (int it = 0; it < 4; it++) {
                int idx = t + it * 256;
                int i  = idx >> 3;
                int k4 = idx & 7;
                float4 v = *reinterpret_cast<const float4*>(X + (size_t)i * DD + d0 + k4 * 4);
                float sc = sinv[i];
                As[(k4 * 4 + 0) * TP + i] = v.x * sc;
                As[(k4 * 4 + 1) * TP + i] = v.y * sc;
                As[(k4 * 4 + 2) * TP + i] = v.z * sc;
                As[(k4 * 4 + 3) * TP + i] = v.w * sc;
            }
            // direct load w1 chunk -> Bs[k][e] (already [d][e] layout)
            #pragma unroll
            for (int it = 0; it < 4; it++) {
                int idx = t + it * 256;
                int k  = idx >> 5;     // 0..31
                int j4 = idx & 31;     // 32 float4 per row
                float4 v = *reinterpret_cast<const float4*>(
                    w1 + (size_t)(d0 + k) * DD + ec * 128 + j4 * 4);
                *reinterpret_cast<float4*>(&Bs[k * TP + j4 * 4]) = v;
            }
            __syncthreads();
            #pragma unroll 8
            for (int kk = 0; kk < 32; kk++) {
                float a[8], b[8];
                #pragma unroll
                for (int i = 0; i < 8; i++) a[i] = As[kk * TP + ty * 8 + i];
                #pragma unroll
                for (int j = 0; j < 8; j++) b[j] = Bs[kk * TP + tx * 8 + j];
                #pragma unroll
                for (int i = 0; i < 8; i++)
                    #pragma unroll
                    for (int j = 0; j < 8; j++) C[i][j] += a[i] * b[j];
            }
            __syncthreads();
        }

        // epilogue: relu + dot with w2 slice
        #pragma unroll
        for (int b = 0; b < 8; b++) {
            int e = ec * 128 + tx * 8 + b;
            float b1e = b1[e];
            float w2e = w2[e];
            #pragma unroll
            for (int a = 0; a < 8; a++) {
                float h = C[a][b] + b1e;
                if (h > 0.f) yacc[a] += h * w2e;
            }
        }
    }

    // cross-tx sum
    float* red = sm;
    #pragma unroll
    for (int a = 0; a < 8; a++) red[(ty * 8 + a) * 16 + tx] = yacc[a];
    __syncthreads();
    if (t < 128) {
        float s = 0.f;
        #pragma unroll
        for (int j = 0; j < 16; j++) s += red[t * 16 + j];
        g_y[rt * LL + t] = s + b2[0];
    }
}

// ---------------------------------------------------------------------------
// Kernel 4: out[b,k,l] = y_ctx[b,k,l] + y_ent[b,k,argmax[b,k,l]]
// (each y already contains +b2, so the sum over p=2 includes 2*b2 as in ref)
// ---------------------------------------------------------------------------
__global__ void finalize_kernel(float* __restrict__ out) {
    int i  = blockIdx.x * 256 + threadIdx.x;
    int bk = i >> 7;
    int l  = i & 127;
    float yc = g_y[(bk * 2) * LL + l];
    float ye = g_y[(bk * 2 + 1) * LL + g_arg[i]];
    out[i] = yc + ye;
}

extern "C" void kernel_launch(void* const* d_in, const int* in_sizes, int n_in,
                              void* d_out, int out_size) {
    const float* context = (const float*)d_in[0];
    const float* w1      = (const float*)d_in[1];
    const float* b1      = (const float*)d_in[2];
    const float* w2      = (const float*)d_in[3];
    const float* b2      = (const float*)d_in[4];
    float* out = (float*)d_out;

    norms_kernel<<<NROWS / 8, 256>>>(context);
    scores_argmax_kernel<<<NBK, 256>>>(context);
    mlp_kernel<<<NROWS / 128, 256>>>(context, w1, b1, w2, b2);
    finalize_kernel<<<NOUT / 256, 256>>>(out);
}

// round 2
// speedup vs baseline: 2.5073x; 2.5073x over previous
#include <cuda_runtime.h>
#include <math.h>
#include <stdint.h>

// Problem constants: B=4, K=64, L=128, D=768
#define NBK   256      // B*K
#define LL    128
#define DD    768
#define NROWS 65536    // NBK * 2 * LL  (all ctx rows + all ent rows)
#define NOUT  32768    // NBK * LL
#define TP    132      // padded smem stride for fp32 SIMT kernels
#define EPSV  1e-8f

// tensor-core MLP smem strides (bank-conflict-free fragment loads)
#define ASTR 36        // A[row][k]: bank=(4r+c)%32 distinct over a frag
#define BSTR 136       // B[k][n]:   bank=(8k+n)%32 distinct over a frag

// Scratch (device globals; no allocation allowed)
__device__ float g_norm[NROWS];
__device__ int   g_arg[NOUT];
__device__ float g_y[NROWS];

// ---------------------------------------------------------------------------
// Kernel 1: L2 norm of every 768-float row
// ---------------------------------------------------------------------------
__global__ void norms_kernel(const float* __restrict__ x) {
    int row  = blockIdx.x * 8 + (threadIdx.x >> 5);
    int lane = threadIdx.x & 31;
    const float4* p = reinterpret_cast<const float4*>(x) + (size_t)row * (DD / 4);
    float s = 0.f;
    #pragma unroll
    for (int i = 0; i < 6; i++) {
        float4 v = p[lane + i * 32];
        s += v.x * v.x + v.y * v.y + v.z * v.z + v.w * v.w;
    }
    #pragma unroll
    for (int o = 16; o; o >>= 1) s += __shfl_xor_sync(0xffffffffu, s, o);
    if (lane == 0) g_norm[row] = sqrtf(s);
}

// ---------------------------------------------------------------------------
// Kernel 2: per (b,k): scores + argmax. Exact fp32 FFMA (argmax gap ~3e-7
// across 32768 rows: tf32 here would flip argmaxes and fail).
// ---------------------------------------------------------------------------
__global__ __launch_bounds__(256) void scores_argmax_kernel(const float* __restrict__ x) {
    __shared__ float sm[2 * 32 * TP];
    float* As = sm;
    float* Bs = sm + 32 * TP;

    int bk = blockIdx.x;
    const float* ctx = x + (size_t)(bk * 2) * LL * DD;
    const float* ent = ctx + (size_t)LL * DD;

    int t  = threadIdx.x;
    int tx = t & 15;
    int ty = t >> 4;

    float C[8][8];
    #pragma unroll
    for (int a = 0; a < 8; a++)
        #pragma unroll
        for (int b = 0; b < 8; b++) C[a][b] = 0.f;

    for (int d0 = 0; d0 < DD; d0 += 32) {
        #pragma unroll
        for (int it = 0; it < 4; it++) {
            int idx = t + it * 256;
            int i  = idx >> 3;
            int k4 = idx & 7;
            float4 v = *reinterpret_cast<const float4*>(ctx + (size_t)i * DD + d0 + k4 * 4);
            As[(k4 * 4 + 0) * TP + i] = v.x;
            As[(k4 * 4 + 1) * TP + i] = v.y;
            As[(k4 * 4 + 2) * TP + i] = v.z;
            As[(k4 * 4 + 3) * TP + i] = v.w;
            float4 w = *reinterpret_cast<const float4*>(ent + (size_t)i * DD + d0 + k4 * 4);
            Bs[(k4 * 4 + 0) * TP + i] = w.x;
            Bs[(k4 * 4 + 1) * TP + i] = w.y;
            Bs[(k4 * 4 + 2) * TP + i] = w.z;
            Bs[(k4 * 4 + 3) * TP + i] = w.w;
        }
        __syncthreads();
        #pragma unroll 8
        for (int kk = 0; kk < 32; kk++) {
            float a[8], b[8];
            #pragma unroll
            for (int i = 0; i < 8; i++) a[i] = As[kk * TP + ty * 8 + i];
            #pragma unroll
            for (int j = 0; j < 8; j++) b[j] = Bs[kk * TP + tx * 8 + j];
            #pragma unroll
            for (int i = 0; i < 8; i++)
                #pragma unroll
                for (int j = 0; j < 8; j++) C[i][j] += a[i] * b[j];
        }
        __syncthreads();
    }

    float nl[8], nm[8];
    #pragma unroll
    for (int a = 0; a < 8; a++) nl[a] = g_norm[(bk * 2) * LL + ty * 8 + a];
    #pragma unroll
    for (int b = 0; b < 8; b++) nm[b] = g_norm[(bk * 2 + 1) * LL + tx * 8 + b];

    float bestv[8];
    int   besti[8];
    #pragma unroll
    for (int a = 0; a < 8; a++) { bestv[a] = -3.4e38f; besti[a] = 0; }
    #pragma unroll
    for (int b = 0; b < 8; b++) {
        #pragma unroll
        for (int a = 0; a < 8; a++) {
            float s = C[a][b] / (nl[a] * nm[b] + EPSV);
            if (s > bestv[a]) { bestv[a] = s; besti[a] = tx * 8 + b; }
        }
    }

    float* rv = sm;
    int*   ri = reinterpret_cast<int*>(sm + 128 * 16);
    #pragma unroll
    for (int a = 0; a < 8; a++) {
        rv[(ty * 8 + a) * 16 + tx] = bestv[a];
        ri[(ty * 8 + a) * 16 + tx] = besti[a];
    }
    __syncthreads();
    if (t < 128) {
        float bv = -3.4e38f; int bi = 0;
        #pragma unroll
        for (int j = 0; j < 16; j++) {
            float v = rv[t * 16 + j];
            if (v > bv) { bv = v; bi = ri[t * 16 + j]; }
        }
        g_arg[bk * LL + t] = bi;
    }
}

// ---------------------------------------------------------------------------
// Kernel 3: fused MLP scalar per normalized row — tf32 tensor cores.
//   y[r] = relu( (x_r/||x_r||) @ W1 + b1 ) @ w2 + b2
// Block: 128 rows; ec loop over 6 N-tiles of 128; K=768 in chunks of 32.
// 8 warps = 4(M) x 2(N); warp tile 32x64 via m16n8k8 tf32 mma.
// ---------------------------------------------------------------------------
__device__ __forceinline__ uint32_t f2tf32(float f) {
    uint32_t u;
    asm("cvt.rna.tf32.f32 %0, %1;" : "=r"(u) : "f"(f));
    return u;
}

__device__ __forceinline__ void mma_tf32(float* d, const uint32_t* a, const uint32_t* b) {
    asm volatile(
        "mma.sync.aligned.m16n8k8.row.col.f32.tf32.tf32.f32 "
        "{%0,%1,%2,%3}, {%4,%5,%6,%7}, {%8,%9}, {%0,%1,%2,%3};"
        : "+f"(d[0]), "+f"(d[1]), "+f"(d[2]), "+f"(d[3])
        : "r"(a[0]), "r"(a[1]), "r"(a[2]), "r"(a[3]), "r"(b[0]), "r"(b[1]));
}

__global__ __launch_bounds__(256, 2) void mlp_tc_kernel(const float* __restrict__ x,
                                                        const float* __restrict__ w1,
                                                        const float* __restrict__ b1,
                                                        const float* __restrict__ w2,
                                                        const float* __restrict__ b2) {
    __shared__ float As[128 * ASTR];   // [row][k] tf32 bits
    __shared__ float Bs[32 * BSTR];    // [k][n]   tf32 bits
    __shared__ float sinv[128];
    __shared__ float sred[128 * 2];

    int rt = blockIdx.x;
    const float* X = x + (size_t)rt * LL * DD;

    int t    = threadIdx.x;
    int lane = t & 31;
    int wid  = t >> 5;
    int wm   = wid & 3;     // warp row: 32 rows
    int wn   = wid >> 2;    // warp col: 64 cols

    if (t < 128) sinv[t] = 1.0f / g_norm[rt * LL + t];

    int lq = lane >> 2;     // 0..7
    int lr = lane & 3;      // 0..3

    float yacc[4] = {0.f, 0.f, 0.f, 0.f}; // rows wm*32 + mi*16 + half*8 + lq

    for (int ec = 0; ec < 6; ec++) {
        float acc[2][8][4];
        #pragma unroll
        for (int mi = 0; mi < 2; mi++)
            #pragma unroll
            for (int ni = 0; ni < 8; ni++)
                #pragma unroll
                for (int c = 0; c < 4; c++) acc[mi][ni][c] = 0.f;

        for (int d0 = 0; d0 < DD; d0 += 32) {
            __syncthreads();
            // A: X chunk scaled by 1/norm, rounded to tf32 -> As[row][k]
            #pragma unroll
            for (int it = 0; it < 4; it++) {
                int idx = t + it * 256;
                int i  = idx >> 3;
                int k4 = idx & 7;
                float4 v = *reinterpret_cast<const float4*>(X + (size_t)i * DD + d0 + k4 * 4);
                float sc = sinv[i];
                uint4 u;
                u.x = f2tf32(v.x * sc);
                u.y = f2tf32(v.y * sc);
                u.z = f2tf32(v.z * sc);
                u.w = f2tf32(v.w * sc);
                *reinterpret_cast<uint4*>(&As[i * ASTR + k4 * 4]) = u;
            }
            // B: w1 chunk -> Bs[k][n], tf32
            #pragma unroll
            for (int it = 0; it < 4; it++) {
                int idx = t + it * 256;
                int k  = idx >> 5;
                int j4 = idx & 31;
                float4 v = *reinterpret_cast<const float4*>(
                    w1 + (size_t)(d0 + k) * DD + ec * 128 + j4 * 4);
                uint4 u;
                u.x = f2tf32(v.x);
                u.y = f2tf32(v.y);
                u.z = f2tf32(v.z);
                u.w = f2tf32(v.w);
                *reinterpret_cast<uint4*>(&Bs[k * BSTR + j4 * 4]) = u;
            }
            __syncthreads();

            const uint32_t* Au = reinterpret_cast<const uint32_t*>(As);
            const uint32_t* Bu = reinterpret_cast<const uint32_t*>(Bs);
            #pragma unroll
            for (int kk = 0; kk < 4; kk++) {
                uint32_t a[2][4];
                #pragma unroll
                for (int mi = 0; mi < 2; mi++) {
                    int rr = wm * 32 + mi * 16 + lq;
                    int cc = kk * 8 + lr;
                    a[mi][0] = Au[rr * ASTR + cc];
                    a[mi][1] = Au[(rr + 8) * ASTR + cc];
                    a[mi][2] = Au[rr * ASTR + cc + 4];
                    a[mi][3] = Au[(rr + 8) * ASTR + cc + 4];
                }
                uint32_t b[8][2];
                #pragma unroll
                for (int ni = 0; ni < 8; ni++) {
                    int nn = wn * 64 + ni * 8 + lq;
                    b[ni][0] = Bu[(kk * 8 + lr) * BSTR + nn];
                    b[ni][1] = Bu[(kk * 8 + lr + 4) * BSTR + nn];
                }
                #pragma unroll
                for (int mi = 0; mi < 2; mi++)
                    #pragma unroll
                    for (int ni = 0; ni < 8; ni++)
                        mma_tf32(acc[mi][ni], a[mi], b[ni]);
            }
        }

        // epilogue: relu + dot with w2 slice (fp32 exact)
        #pragma unroll
        for (int ni = 0; ni < 8; ni++) {
            int e0 = ec * 128 + wn * 64 + ni * 8 + lr * 2;
            float b1a = __ldg(b1 + e0),     b1b = __ldg(b1 + e0 + 1);
            float w2a = __ldg(w2 + e0),     w2b = __ldg(w2 + e0 + 1);
            #pragma unroll
            for (int mi = 0; mi < 2; mi++) {
                float h;
                h = acc[mi][ni][0] + b1a; if (h > 0.f) yacc[mi * 2 + 0] += h * w2a;
                h = acc[mi][ni][1] + b1b; if (h > 0.f) yacc[mi * 2 + 0] += h * w2b;
                h = acc[mi][ni][2] + b1a; if (h > 0.f) yacc[mi * 2 + 1] += h * w2a;
                h = acc[mi][ni][3] + b1b; if (h > 0.f) yacc[mi * 2 + 1] += h * w2b;
            }
        }
    }

    // reduce over lanes sharing a row (lane&3), then over the two warp_n
    #pragma unroll
    for (int j = 0; j < 4; j++) {
        yacc[j] += __shfl_xor_sync(0xffffffffu, yacc[j], 1);
        yacc[j] += __shfl_xor_sync(0xffffffffu, yacc[j], 2);
    }
    if (lr == 0) {
        #pragma unroll
        for (int j = 0; j < 4; j++) {
            int row = wm * 32 + (j >> 1) * 16 + (j & 1) * 8 + lq;
            sred[row * 2 + wn] = yacc[j];
        }
    }
    __syncthreads();
    if (t < 128)
        g_y[rt * LL + t] = sred[t * 2] + sred[t * 2 + 1] + b2[0];
}

// ---------------------------------------------------------------------------
// Kernel 4: out[b,k,l] = y_ctx[b,k,l] + y_ent[b,k,argmax[b,k,l]]
// ---------------------------------------------------------------------------
__global__ void finalize_kernel(float* __restrict__ out) {
    int i  = blockIdx.x * 256 + threadIdx.x;
    int bk = i >> 7;
    float yc = g_y[(bk * 2) * LL + (i & 127)];
    float ye = g_y[(bk * 2 + 1) * LL + g_arg[i]];
    out[i] = yc + ye;
}

extern "C" void kernel_launch(void* const* d_in, const int* in_sizes, int n_in,
                              void* d_out, int out_size) {
    const float* context = (const float*)d_in[0];
    const float* w1      = (const float*)d_in[1];
    const float* b1      = (const float*)d_in[2];
    const float* w2      = (const float*)d_in[3];
    const float* b2      = (const float*)d_in[4];
    float* out = (float*)d_out;

    norms_kernel<<<NROWS / 8, 256>>>(context);
    scores_argmax_kernel<<<NBK, 256>>>(context);
    mlp_tc_kernel<<<NROWS / 128, 256>>>(context, w1, b1, w2, b2);
    finalize_kernel<<<NOUT / 256, 256>>>(out);
}

// round 4
// speedup vs baseline: 2.5587x; 1.0205x over previous
#include <cuda_runtime.h>
#include <math.h>
#include <stdint.h>

// Problem constants: B=4, K=64, L=128, D=768
#define NBK   256
#define LL    128
#define DD    768
#define NROWS 65536
#define NOUT  32768
#define TP    132
#define EPSV  1e-8f

#define ASTR 36        // A[row][k]: bank=(4r+c)%32 conflict-free frags
#define BSTR 136       // B[k][n]:   bank=(8k+n)%32 conflict-free frags

// Scratch
__device__ float    g_norm[NROWS];
__device__ int      g_arg[NOUT];
__device__ float    g_y[NROWS];
__device__ uint32_t g_w1t32[DD * DD];   // w1 pre-rounded to tf32 bits, [d][e]

__device__ __forceinline__ uint32_t f2tf32(float f) {
    uint32_t u;
    asm("cvt.rna.tf32.f32 %0, %1;" : "=r"(u) : "f"(f));
    return u;
}

__device__ __forceinline__ void mma_tf32(float* d, const uint32_t* a, const uint32_t* b) {
    asm volatile(
        "mma.sync.aligned.m16n8k8.row.col.f32.tf32.tf32.f32 "
        "{%0,%1,%2,%3}, {%4,%5,%6,%7}, {%8,%9}, {%0,%1,%2,%3};"
        : "+f"(d[0]), "+f"(d[1]), "+f"(d[2]), "+f"(d[3])
        : "r"(a[0]), "r"(a[1]), "r"(a[2]), "r"(a[3]), "r"(b[0]), "r"(b[1]));
}

// ---------------------------------------------------------------------------
// Kernel 0: w1 -> tf32 bits (removes cvt from the MLP hot loop)
// ---------------------------------------------------------------------------
__global__ void prep_w1_kernel(const float* __restrict__ w1) {
    int i = blockIdx.x * 256 + threadIdx.x;
    if (i < DD * DD) g_w1t32[i] = f2tf32(__ldg(w1 + i));
}

// ---------------------------------------------------------------------------
// Kernel 1: scores + argmax (exact fp32 FFMA) with FUSED row norms.
// Norms accumulated during tile loads; written to g_norm for the MLP kernel.
// ---------------------------------------------------------------------------
__global__ __launch_bounds__(256) void scores_argmax_kernel(const float* __restrict__ x) {
    __shared__ float sm[2 * 32 * TP];
    __shared__ float snA[128];
    __shared__ float snB[128];
    float* As = sm;
    float* Bs = sm + 32 * TP;

    int bk = blockIdx.x;
    const float* ctx = x + (size_t)(bk * 2) * LL * DD;
    const float* ent = ctx + (size_t)LL * DD;

    int t  = threadIdx.x;
    int tx = t & 15;
    int ty = t >> 4;

    float C[8][8];
    #pragma unroll
    for (int a = 0; a < 8; a++)
        #pragma unroll
        for (int b = 0; b < 8; b++) C[a][b] = 0.f;

    float ssA[4] = {0.f, 0.f, 0.f, 0.f};
    float ssB[4] = {0.f, 0.f, 0.f, 0.f};

    for (int d0 = 0; d0 < DD; d0 += 32) {
        #pragma unroll
        for (int it = 0; it < 4; it++) {
            int idx = t + it * 256;
            int i  = idx >> 3;
            int k4 = idx & 7;
            float4 v = *reinterpret_cast<const float4*>(ctx + (size_t)i * DD + d0 + k4 * 4);
            ssA[it] += v.x * v.x + v.y * v.y + v.z * v.z + v.w * v.w;
            As[(k4 * 4 + 0) * TP + i] = v.x;
            As[(k4 * 4 + 1) * TP + i] = v.y;
            As[(k4 * 4 + 2) * TP + i] = v.z;
            As[(k4 * 4 + 3) * TP + i] = v.w;
            float4 w = *reinterpret_cast<const float4*>(ent + (size_t)i * DD + d0 + k4 * 4);
            ssB[it] += w.x * w.x + w.y * w.y + w.z * w.z + w.w * w.w;
            Bs[(k4 * 4 + 0) * TP + i] = w.x;
            Bs[(k4 * 4 + 1) * TP + i] = w.y;
            Bs[(k4 * 4 + 2) * TP + i] = w.z;
            Bs[(k4 * 4 + 3) * TP + i] = w.w;
        }
        __syncthreads();
        #pragma unroll 8
        for (int kk = 0; kk < 32; kk++) {
            float a[8], b[8];
            #pragma unroll
            for (int i = 0; i < 8; i++) a[i] = As[kk * TP + ty * 8 + i];
            #pragma unroll
            for (int j = 0; j < 8; j++) b[j] = Bs[kk * TP + tx * 8 + j];
            #pragma unroll
            for (int i = 0; i < 8; i++)
                #pragma unroll
                for (int j = 0; j < 8; j++) C[i][j] += a[i] * b[j];
        }
        __syncthreads();
    }

    // finish norms: reduce over the 8 lanes sharing a row, write smem + global
    #pragma unroll
    for (int it = 0; it < 4; it++) {
        float sA = ssA[it], sB = ssB[it];
        #pragma unroll
        for (int o = 1; o < 8; o <<= 1) {
            sA += __shfl_xor_sync(0xffffffffu, sA, o);
            sB += __shfl_xor_sync(0xffffffffu, sB, o);
        }
        if ((t & 7) == 0) {
            int row = (t + it * 256) >> 3;
            float na = sqrtf(sA), nb = sqrtf(sB);
            snA[row] = na;
            snB[row] = nb;
            g_norm[(bk * 2) * LL + row]     = na;
            g_norm[(bk * 2 + 1) * LL + row] = nb;
        }
    }
    __syncthreads();

    float nl[8], nm[8];
    #pragma unroll
    for (int a = 0; a < 8; a++) nl[a] = snA[ty * 8 + a];
    #pragma unroll
    for (int b = 0; b < 8; b++) nm[b] = snB[tx * 8 + b];

    float bestv[8];
    int   besti[8];
    #pragma unroll
    for (int a = 0; a < 8; a++) { bestv[a] = -3.4e38f; besti[a] = 0; }
    #pragma unroll
    for (int b = 0; b < 8; b++) {
        #pragma unroll
        for (int a = 0; a < 8; a++) {
            float s = C[a][b] / (nl[a] * nm[b] + EPSV);
            if (s > bestv[a]) { bestv[a] = s; besti[a] = tx * 8 + b; }
        }
    }

    float* rv = sm;
    int*   ri = reinterpret_cast<int*>(sm + 128 * 16);
    #pragma unroll
    for (int a = 0; a < 8; a++) {
        rv[(ty * 8 + a) * 16 + tx] = bestv[a];
        ri[(ty * 8 + a) * 16 + tx] = besti[a];
    }
    __syncthreads();
    if (t < 128) {
        float bv = -3.4e38f; int bi = 0;
        #pragma unroll
        for (int j = 0; j < 16; j++) {
            float v = rv[t * 16 + j];
            if (v > bv) { bv = v; bi = ri[t * 16 + j]; }
        }
        g_arg[bk * LL + t] = bi;
    }
}

// ---------------------------------------------------------------------------
// Kernel 2: MLP via tf32 mma.sync, software-pipelined (double-buffered smem).
// Per block: 128 rows; ec loop over 6 N-tiles of 128; K=768 in chunks of 32.
// 8 warps = 4(M) x 2(N); warp tile 32x64 via m16n8k8.
// ---------------------------------------------------------------------------
#define MLP_OFF_AS   0                         // 2 x 128*36 u32 = 36864 B
#define MLP_OFF_BS   36864                     // 2 x 32*136 u32 = 34816 B
#define MLP_OFF_SINV 71680                     // 128 f32
#define MLP_OFF_SRED 72192                     // 256 f32
#define MLP_SMEM     73216

__global__ __launch_bounds__(256, 1) void mlp_tc_kernel(const float* __restrict__ x,
                                                        const float* __restrict__ b1,
                                                        const float* __restrict__ w2,
                                                        const float* __restrict__ b2) {
    extern __shared__ char smem[];
    uint32_t* As   = reinterpret_cast<uint32_t*>(smem + MLP_OFF_AS);
    uint32_t* Bs   = reinterpret_cast<uint32_t*>(smem + MLP_OFF_BS);
    float*    sinv = reinterpret_cast<float*>(smem + MLP_OFF_SINV);
    float*    sred = reinterpret_cast<float*>(smem + MLP_OFF_SRED);

    int rt = blockIdx.x;
    const float* X = x + (size_t)rt * LL * DD;

    int t    = threadIdx.x;
    int lane = t & 31;
    int wid  = t >> 5;
    int wm   = wid & 3;
    int wn   = wid >> 2;
    int lq   = lane >> 2;
    int lr   = lane & 3;

    if (t < 128) sinv[t] = 1.0f / g_norm[rt * LL + t];
    __syncthreads();

    // per-thread load geometry (fixed across chunks)
    int arow[4], ak4[4], bk_[4], bj4[4];
    #pragma unroll
    for (int it = 0; it < 4; it++) {
        int idx = t + it * 256;
        arow[it] = idx >> 3;  ak4[it] = idx & 7;
        bk_[it]  = idx >> 5;  bj4[it] = idx & 31;
    }

    float yacc[4] = {0.f, 0.f, 0.f, 0.f};

    for (int ec = 0; ec < 6; ec++) {
        float acc[2][8][4];
        #pragma unroll
        for (int mi = 0; mi < 2; mi++)
            #pragma unroll
            for (int ni = 0; ni < 8; ni++)
                #pragma unroll
                for (int c = 0; c < 4; c++) acc[mi][ni][c] = 0.f;

        float4 av[4];
        uint4  bv[4];
        // prologue: load chunk 0
        #pragma unroll
        for (int it = 0; it < 4; it++) {
            av[it] = *reinterpret_cast<const float4*>(X + (size_t)arow[it] * DD + ak4[it] * 4);
            bv[it] = *reinterpret_cast<const uint4*>(g_w1t32 + (size_t)bk_[it] * DD + ec * 128 + bj4[it] * 4);
        }
        // store chunk 0 -> buf 0
        #pragma unroll
        for (int it = 0; it < 4; it++) {
            float sc = sinv[arow[it]];
            uint4 u;
            u.x = f2tf32(av[it].x * sc); u.y = f2tf32(av[it].y * sc);
            u.z = f2tf32(av[it].z * sc); u.w = f2tf32(av[it].w * sc);
            *reinterpret_cast<uint4*>(&As[arow[it] * ASTR + ak4[it] * 4]) = u;
            *reinterpret_cast<uint4*>(&Bs[bk_[it] * BSTR + bj4[it] * 4]) = bv[it];
        }
        __syncthreads();

        for (int c = 0; c < 24; c++) {
            int buf = c & 1;
            if (c < 23) {
                int d0 = (c + 1) * 32;
                #pragma unroll
                for (int it = 0; it < 4; it++) {
                    av[it] = *reinterpret_cast<const float4*>(X + (size_t)arow[it] * DD + d0 + ak4[it] * 4);
                    bv[it] = *reinterpret_cast<const uint4*>(g_w1t32 + (size_t)(d0 + bk_[it]) * DD + ec * 128 + bj4[it] * 4);
                }
            }
            // compute current buffer
            const uint32_t* Au = As + buf * (128 * ASTR);
            const uint32_t* Bu = Bs + buf * (32 * BSTR);
            #pragma unroll
            for (int kk = 0; kk < 4; kk++) {
                uint32_t a[2][4];
                #pragma unroll
                for (int mi = 0; mi < 2; mi++) {
                    int rr = wm * 32 + mi * 16 + lq;
                    int cc = kk * 8 + lr;
                    a[mi][0] = Au[rr * ASTR + cc];
                    a[mi][1] = Au[(rr + 8) * ASTR + cc];
                    a[mi][2] = Au[rr * ASTR + cc + 4];
                    a[mi][3] = Au[(rr + 8) * ASTR + cc + 4];
                }
                uint32_t b[8][2];
                #pragma unroll
                for (int ni = 0; ni < 8; ni++) {
                    int nn = wn * 64 + ni * 8 + lq;
                    b[ni][0] = Bu[(kk * 8 + lr) * BSTR + nn];
                    b[ni][1] = Bu[(kk * 8 + lr + 4) * BSTR + nn];
                }
                #pragma unroll
                for (int mi = 0; mi < 2; mi++)
                    #pragma unroll
                    for (int ni = 0; ni < 8; ni++)
                        mma_tf32(acc[mi][ni], a[mi], b[ni]);
            }
            // store next chunk into the other buffer
            if (c < 23) {
                uint32_t* Ad = As + (buf ^ 1) * (128 * ASTR);
                uint32_t* Bd = Bs + (buf ^ 1) * (32 * BSTR);
                #pragma unroll
                for (int it = 0; it < 4; it++) {
                    float sc = sinv[arow[it]];
                    uint4 u;
                    u.x = f2tf32(av[it].x * sc); u.y = f2tf32(av[it].y * sc);
                    u.z = f2tf32(av[it].z * sc); u.w = f2tf32(av[it].w * sc);
                    *reinterpret_cast<uint4*>(&Ad[arow[it] * ASTR + ak4[it] * 4]) = u;
                    *reinterpret_cast<uint4*>(&Bd[bk_[it] * BSTR + bj4[it] * 4]) = bv[it];
                }
            }
            __syncthreads();
        }

        // epilogue: relu + dot with w2 slice (fp32 exact)
        #pragma unroll
        for (int ni = 0; ni < 8; ni++) {
            int e0 = ec * 128 + wn * 64 + ni * 8 + lr * 2;
            float b1a = __ldg(b1 + e0),     b1b = __ldg(b1 + e0 + 1);
            float w2a = __ldg(w2 + e0),     w2b = __ldg(w2 + e0 + 1);
            #pragma unroll
            for (int mi = 0; mi < 2; mi++) {
                float h;
                h = acc[mi][ni][0] + b1a; if (h > 0.f) yacc[mi * 2 + 0] += h * w2a;
                h = acc[mi][ni][1] + b1b; if (h > 0.f) yacc[mi * 2 + 0] += h * w2b;
                h = acc[mi][ni][2] + b1a; if (h > 0.f) yacc[mi * 2 + 1] += h * w2a;
                h = acc[mi][ni][3] + b1b; if (h > 0.f) yacc[mi * 2 + 1] += h * w2b;
            }
        }
    }

    // reduce lanes sharing a row (lr), then the two warp_n halves via smem
    #pragma unroll
    for (int j = 0; j < 4; j++) {
        yacc[j] += __shfl_xor_sync(0xffffffffu, yacc[j], 1);
        yacc[j] += __shfl_xor_sync(0xffffffffu, yacc[j], 2);
    }
    if (lr == 0) {
        #pragma unroll
        for (int j = 0; j < 4; j++) {
            int row = wm * 32 + (j >> 1) * 16 + (j & 1) * 8 + lq;
            sred[row * 2 + wn] = yacc[j];
        }
    }
    __syncthreads();
    if (t < 128)
        g_y[rt * LL + t] = sred[t * 2] + sred[t * 2 + 1] + __ldg(b2);
}

// ---------------------------------------------------------------------------
// Kernel 3: out[b,k,l] = y_ctx[b,k,l] + y_ent[b,k,argmax[b,k,l]]
// ---------------------------------------------------------------------------
__global__ void finalize_kernel(float* __restrict__ out) {
    int i  = blockIdx.x * 256 + threadIdx.x;
    int bk = i >> 7;
    float yc = g_y[(bk * 2) * LL + (i & 127)];
    float ye = g_y[(bk * 2 + 1) * LL + g_arg[i]];
    out[i] = yc + ye;
}

extern "C" void kernel_launch(void* const* d_in, const int* in_sizes, int n_in,
                              void* d_out, int out_size) {
    const float* context = (const float*)d_in[0];
    const float* w1      = (const float*)d_in[1];
    const float* b1      = (const float*)d_in[2];
    const float* w2      = (const float*)d_in[3];
    const float* b2      = (const float*)d_in[4];
    float* out = (float*)d_out;

    cudaFuncSetAttribute(mlp_tc_kernel,
                         cudaFuncAttributeMaxDynamicSharedMemorySize, MLP_SMEM);

    prep_w1_kernel<<<(DD * DD + 255) / 256, 256>>>(w1);
    scores_argmax_kernel<<<NBK, 256>>>(context);
    mlp_tc_kernel<<<NROWS / 128, 256, MLP_SMEM>>>(context, b1, w2, b2);
    finalize_kernel<<<NOUT / 256, 256>>>(out);
}

// round 5
// speedup vs baseline: 3.9031x; 1.5254x over previous
#include <cuda_runtime.h>
#include <cuda_fp16.h>
#include <math.h>
#include <stdint.h>

// Problem constants: B=4, K=64, L=128, D=768
#define NBK   256
#define LL    128
#define DD    768
#define NROWS 65536
#define NOUT  32768
#define TP    132
#define EPSV  1e-8f

#define ASTRH 40   // fp16 smem row stride (80 B) -> ldmatrix conflict-free

// Scratch
__device__ float  g_norm[NROWS];
__device__ int    g_arg[NOUT];
__device__ float  g_y[NROWS];
__device__ __half g_w1h[DD * DD];   // w1^T as fp16, [e][d] (n-major, k-contig)

__device__ __forceinline__ void ldsm_x4(uint32_t* r, uint32_t addr) {
    asm volatile("ldmatrix.sync.aligned.m8n8.x4.shared.b16 {%0,%1,%2,%3}, [%4];"
        : "=r"(r[0]), "=r"(r[1]), "=r"(r[2]), "=r"(r[3]) : "r"(addr));
}
__device__ __forceinline__ void mma_fp16(float* d, const uint32_t* a, const uint32_t* b) {
    asm volatile(
        "mma.sync.aligned.m16n8k16.row.col.f32.f16.f16.f32 "
        "{%0,%1,%2,%3}, {%4,%5,%6,%7}, {%8,%9}, {%0,%1,%2,%3};"
        : "+f"(d[0]), "+f"(d[1]), "+f"(d[2]), "+f"(d[3])
        : "r"(a[0]), "r"(a[1]), "r"(a[2]), "r"(a[3]), "r"(b[0]), "r"(b[1]));
}
__device__ __forceinline__ uint32_t smem_u32(const void* p) {
    uint32_t a;
    asm("{ .reg .u64 t; cvta.to.shared.u64 t, %1; cvt.u32.u64 %0, t; }" : "=r"(a) : "l"(p));
    return a;
}
__device__ __forceinline__ uint32_t pack2(float x, float y) {
    __half2 h = __floats2half2_rn(x, y);
    return *reinterpret_cast<uint32_t*>(&h);
}

// ---------------------------------------------------------------------------
// Kernel 0: w1 -> fp16, transposed to [e][d]
// ---------------------------------------------------------------------------
__global__ void prep_w1_kernel(const float* __restrict__ w1) {
    int e = blockIdx.x;
    for (int d = threadIdx.x; d < DD; d += 256)
        g_w1h[e * DD + d] = __float2half_rn(__ldg(w1 + (size_t)d * DD + e));
}

// ---------------------------------------------------------------------------
// Kernel 1: scores + argmax (exact fp32 FFMA) with fused row norms.
// ---------------------------------------------------------------------------
__global__ __launch_bounds__(256) void scores_argmax_kernel(const float* __restrict__ x) {
    __shared__ float sm[2 * 32 * TP];
    __shared__ float snA[128];
    __shared__ float snB[128];
    float* As = sm;
    float* Bs = sm + 32 * TP;

    int bk = blockIdx.x;
    const float* ctx = x + (size_t)(bk * 2) * LL * DD;
    const float* ent = ctx + (size_t)LL * DD;

    int t  = threadIdx.x;
    int tx = t & 15;
    int ty = t >> 4;

    float C[8][8];
    #pragma unroll
    for (int a = 0; a < 8; a++)
        #pragma unroll
        for (int b = 0; b < 8; b++) C[a][b] = 0.f;

    float ssA[4] = {0.f, 0.f, 0.f, 0.f};
    float ssB[4] = {0.f, 0.f, 0.f, 0.f};

    for (int d0 = 0; d0 < DD; d0 += 32) {
        #pragma unroll
        for (int it = 0; it < 4; it++) {
            int idx = t + it * 256;
            int i  = idx >> 3;
            int k4 = idx & 7;
            float4 v = *reinterpret_cast<const float4*>(ctx + (size_t)i * DD + d0 + k4 * 4);
            ssA[it] += v.x * v.x + v.y * v.y + v.z * v.z + v.w * v.w;
            As[(k4 * 4 + 0) * TP + i] = v.x;
            As[(k4 * 4 + 1) * TP + i] = v.y;
            As[(k4 * 4 + 2) * TP + i] = v.z;
            As[(k4 * 4 + 3) * TP + i] = v.w;
            float4 w = *reinterpret_cast<const float4*>(ent + (size_t)i * DD + d0 + k4 * 4);
            ssB[it] += w.x * w.x + w.y * w.y + w.z * w.z + w.w * w.w;
            Bs[(k4 * 4 + 0) * TP + i] = w.x;
            Bs[(k4 * 4 + 1) * TP + i] = w.y;
            Bs[(k4 * 4 + 2) * TP + i] = w.z;
            Bs[(k4 * 4 + 3) * TP + i] = w.w;
        }
        __syncthreads();
        #pragma unroll 8
        for (int kk = 0; kk < 32; kk++) {
            float a[8], b[8];
            #pragma unroll
            for (int i = 0; i < 8; i++) a[i] = As[kk * TP + ty * 8 + i];
            #pragma unroll
            for (int j = 0; j < 8; j++) b[j] = Bs[kk * TP + tx * 8 + j];
            #pragma unroll
            for (int i = 0; i < 8; i++)
                #pragma unroll
                for (int j = 0; j < 8; j++) C[i][j] += a[i] * b[j];
        }
        __syncthreads();
    }

    #pragma unroll
    for (int it = 0; it < 4; it++) {
        float sA = ssA[it], sB = ssB[it];
        #pragma unroll
        for (int o = 1; o < 8; o <<= 1) {
            sA += __shfl_xor_sync(0xffffffffu, sA, o);
            sB += __shfl_xor_sync(0xffffffffu, sB, o);
        }
        if ((t & 7) == 0) {
            int row = (t + it * 256) >> 3;
            float na = sqrtf(sA), nb = sqrtf(sB);
            snA[row] = na;
            snB[row] = nb;
            g_norm[(bk * 2) * LL + row]     = na;
            g_norm[(bk * 2 + 1) * LL + row] = nb;
        }
    }
    __syncthreads();

    float nl[8], nm[8];
    #pragma unroll
    for (int a = 0; a < 8; a++) nl[a] = snA[ty * 8 + a];
    #pragma unroll
    for (int b = 0; b < 8; b++) nm[b] = snB[tx * 8 + b];

    float bestv[8];
    int   besti[8];
    #pragma unroll
    for (int a = 0; a < 8; a++) { bestv[a] = -3.4e38f; besti[a] = 0; }
    #pragma unroll
    for (int b = 0; b < 8; b++) {
        #pragma unroll
        for (int a = 0; a < 8; a++) {
            float s = C[a][b] / (nl[a] * nm[b] + EPSV);
            if (s > bestv[a]) { bestv[a] = s; besti[a] = tx * 8 + b; }
        }
    }

    float* rv = sm;
    int*   ri = reinterpret_cast<int*>(sm + 128 * 16);
    #pragma unroll
    for (int a = 0; a < 8; a++) {
        rv[(ty * 8 + a) * 16 + tx] = bestv[a];
        ri[(ty * 8 + a) * 16 + tx] = besti[a];
    }
    __syncthreads();
    if (t < 128) {
        float bv = -3.4e38f; int bi = 0;
        #pragma unroll
        for (int j = 0; j < 16; j++) {
            float v = rv[t * 16 + j];
            if (v > bv) { bv = v; bi = ri[t * 16 + j]; }
        }
        g_arg[bk * LL + t] = bi;
    }
}

// ---------------------------------------------------------------------------
// Kernel 2: MLP via fp16 m16n8k16 mma.sync + ldmatrix, double-buffered.
// Per block: 128 rows; 6 N-tiles of 128; K=768 in chunks of 32.
// 8 warps = 4(M) x 2(N); warp tile 32x64.
// ---------------------------------------------------------------------------
#define ABUF (128 * ASTRH)          // halves per A buffer (5120)
#define BBUF (128 * ASTRH)          // halves per B buffer
#define MLP_OFF_AS   0                          // 2 x 10240 B
#define MLP_OFF_BS   20480                      // 2 x 10240 B
#define MLP_OFF_SINV 40960                      // 128 f32
#define MLP_OFF_SRED 41472                      // 256 f32
#define MLP_SMEM     42496

__global__ __launch_bounds__(256, 2) void mlp_tc_kernel(const float* __restrict__ x,
                                                        const float* __restrict__ b1,
                                                        const float* __restrict__ w2,
                                                        const float* __restrict__ b2) {
    extern __shared__ char smem[];
    __half* As   = reinterpret_cast<__half*>(smem + MLP_OFF_AS);
    __half* Bs   = reinterpret_cast<__half*>(smem + MLP_OFF_BS);
    float*  sinv = reinterpret_cast<float*>(smem + MLP_OFF_SINV);
    float*  sred = reinterpret_cast<float*>(smem + MLP_OFF_SRED);
    uint32_t as_u32 = smem_u32(As);
    uint32_t bs_u32 = smem_u32(Bs);

    int rt = blockIdx.x;
    const float* X = x + (size_t)rt * LL * DD;

    int t    = threadIdx.x;
    int lane = t & 31;
    int wid  = t >> 5;
    int wm   = wid & 3;
    int wn   = wid >> 2;
    int lq   = lane >> 2;
    int lr   = lane & 3;

    if (t < 128) sinv[t] = 1.0f / g_norm[rt * LL + t];
    __syncthreads();

    // global-load geometry (fixed)
    int arow[4], ak4[4];
    #pragma unroll
    for (int it = 0; it < 4; it++) {
        int idx = t + it * 256;
        arow[it] = idx >> 3;  ak4[it] = idx & 7;
    }
    int bn[2], bj[2];
    #pragma unroll
    for (int it = 0; it < 2; it++) {
        int idx = t + it * 256;
        bn[it] = idx >> 2;  bj[it] = idx & 3;
    }

    // ldmatrix address bases (bytes)
    uint32_t a_frag_base = as_u32 +
        (uint32_t)(((wm * 32 + (lane & 15)) * ASTRH + (lane >> 4) * 8) * 2);
    uint32_t b_row_off = ((lane >> 4) * 8 + (lane & 7));
    uint32_t b_k_off   = ((lane >> 3) & 1) * 8;
    uint32_t b_frag_base = bs_u32 +
        (uint32_t)(((wn * 64 + b_row_off) * ASTRH + b_k_off) * 2);

    float yacc[4] = {0.f, 0.f, 0.f, 0.f};

    for (int ec = 0; ec < 6; ec++) {
        float acc[2][8][4];
        #pragma unroll
        for (int mi = 0; mi < 2; mi++)
            #pragma unroll
            for (int ni = 0; ni < 8; ni++)
                #pragma unroll
                for (int c = 0; c < 4; c++) acc[mi][ni][c] = 0.f;

        float4 av[4];
        uint4  bv[2];
        // prologue: load + store chunk 0 into buf 0
        #pragma unroll
        for (int it = 0; it < 4; it++)
            av[it] = *reinterpret_cast<const float4*>(X + (size_t)arow[it] * DD + ak4[it] * 4);
        #pragma unroll
        for (int it = 0; it < 2; it++)
            bv[it] = *reinterpret_cast<const uint4*>(&g_w1h[(size_t)(ec * 128 + bn[it]) * DD + bj[it] * 8]);
        #pragma unroll
        for (int it = 0; it < 4; it++) {
            float sc = sinv[arow[it]];
            uint2 u;
            u.x = pack2(av[it].x * sc, av[it].y * sc);
            u.y = pack2(av[it].z * sc, av[it].w * sc);
            *reinterpret_cast<uint2*>(&As[arow[it] * ASTRH + ak4[it] * 4]) = u;
        }
        #pragma unroll
        for (int it = 0; it < 2; it++)
            *reinterpret_cast<uint4*>(&Bs[bn[it] * ASTRH + bj[it] * 8]) = bv[it];
        __syncthreads();

        for (int c = 0; c < 24; c++) {
            int buf = c & 1;
            if (c < 23) {
                int d0 = (c + 1) * 32;
                #pragma unroll
                for (int it = 0; it < 4; it++)
                    av[it] = *reinterpret_cast<const float4*>(X + (size_t)arow[it] * DD + d0 + ak4[it] * 4);
                #pragma unroll
                for (int it = 0; it < 2; it++)
                    bv[it] = *reinterpret_cast<const uint4*>(&g_w1h[(size_t)(ec * 128 + bn[it]) * DD + d0 + bj[it] * 8]);
            }
            // compute on current buffer
            uint32_t abase = a_frag_base + buf * (ABUF * 2);
            uint32_t bbase = b_frag_base + buf * (BBUF * 2);
            #pragma unroll
            for (int kk = 0; kk < 2; kk++) {
                uint32_t a[2][4];
                #pragma unroll
                for (int mi = 0; mi < 2; mi++)
                    ldsm_x4(a[mi], abase + mi * (16 * ASTRH * 2) + kk * 32);
                uint32_t b[4][4];
                #pragma unroll
                for (int nb = 0; nb < 4; nb++)
                    ldsm_x4(b[nb], bbase + nb * (16 * ASTRH * 2) + kk * 32);
                #pragma unroll
                for (int mi = 0; mi < 2; mi++)
                    #pragma unroll
                    for (int nb = 0; nb < 4; nb++) {
                        mma_fp16(acc[mi][nb * 2 + 0], a[mi], &b[nb][0]);
                        mma_fp16(acc[mi][nb * 2 + 1], a[mi], &b[nb][2]);
                    }
            }
            // store next chunk into other buffer
            if (c < 23) {
                __half* Ad = As + (buf ^ 1) * ABUF;
                __half* Bd = Bs + (buf ^ 1) * BBUF;
                #pragma unroll
                for (int it = 0; it < 4; it++) {
                    float sc = sinv[arow[it]];
                    uint2 u;
                    u.x = pack2(av[it].x * sc, av[it].y * sc);
                    u.y = pack2(av[it].z * sc, av[it].w * sc);
                    *reinterpret_cast<uint2*>(&Ad[arow[it] * ASTRH + ak4[it] * 4]) = u;
                }
                #pragma unroll
                for (int it = 0; it < 2; it++)
                    *reinterpret_cast<uint4*>(&Bd[bn[it] * ASTRH + bj[it] * 8]) = bv[it];
            }
            __syncthreads();
        }

        // epilogue: relu + dot with w2 slice (fp32 exact)
        #pragma unroll
        for (int ni = 0; ni < 8; ni++) {
            int e0 = ec * 128 + wn * 64 + ni * 8 + lr * 2;
            float b1a = __ldg(b1 + e0),     b1b = __ldg(b1 + e0 + 1);
            float w2a = __ldg(w2 + e0),     w2b = __ldg(w2 + e0 + 1);
            #pragma unroll
            for (int mi = 0; mi < 2; mi++) {
                float h;
                h = acc[mi][ni][0] + b1a; if (h > 0.f) yacc[mi * 2 + 0] += h * w2a;
                h = acc[mi][ni][1] + b1b; if (h > 0.f) yacc[mi * 2 + 0] += h * w2b;
                h = acc[mi][ni][2] + b1a; if (h > 0.f) yacc[mi * 2 + 1] += h * w2a;
                h = acc[mi][ni][3] + b1b; if (h > 0.f) yacc[mi * 2 + 1] += h * w2b;
            }
        }
    }

    // reduce lanes sharing a row, then the two warp_n halves
    #pragma unroll
    for (int j = 0; j < 4; j++) {
        yacc[j] += __shfl_xor_sync(0xffffffffu, yacc[j], 1);
        yacc[j] += __shfl_xor_sync(0xffffffffu, yacc[j], 2);
    }
    if (lr == 0) {
        #pragma unroll
        for (int j = 0; j < 4; j++) {
            int row = wm * 32 + (j >> 1) * 16 + (j & 1) * 8 + lq;
            sred[row * 2 + wn] = yacc[j];
        }
    }
    __syncthreads();
    if (t < 128)
        g_y[rt * LL + t] = sred[t * 2] + sred[t * 2 + 1] + __ldg(b2);
}

// ---------------------------------------------------------------------------
// Kernel 3: out = y_ctx + y_ent[argmax]
// ---------------------------------------------------------------------------
__global__ void finalize_kernel(float* __restrict__ out) {
    int i  = blockIdx.x * 256 + threadIdx.x;
    int bk = i >> 7;
    float yc = g_y[(bk * 2) * LL + (i & 127)];
    float ye = g_y[(bk * 2 + 1) * LL + g_arg[i]];
    out[i] = yc + ye;
}

extern "C" void kernel_launch(void* const* d_in, const int* in_sizes, int n_in,
                              void* d_out, int out_size) {
    const float* context = (const float*)d_in[0];
    const float* w1      = (const float*)d_in[1];
    const float* b1      = (const float*)d_in[2];
    const float* w2      = (const float*)d_in[3];
    const float* b2      = (const float*)d_in[4];
    float* out = (float*)d_out;

    cudaFuncSetAttribute(mlp_tc_kernel,
                         cudaFuncAttributeMaxDynamicSharedMemorySize, MLP_SMEM);

    prep_w1_kernel<<<DD, 256>>>(w1);
    scores_argmax_kernel<<<NBK, 256>>>(context);
    mlp_tc_kernel<<<NROWS / 128, 256, MLP_SMEM>>>(context, b1, w2, b2);
    finalize_kernel<<<NOUT / 256, 256>>>(out);
}